// round 8
// baseline (speedup 1.0000x reference)
#include <cuda_runtime.h>

#define IMG    1024
#define OUTD   1016
#define TILE_W 128
#define TILE_H 32
#define IN_H   (TILE_H + 8)    // 40 input rows
#define MID_W  132             // horizontal-sum cols
#define MID_H  (TILE_H + 4)    // 36 deviation rows
#define HS     136             // smem row stride (floats)
#define NT     320
#define NW     (NT / 32)       // 10 warps

__device__ __forceinline__ float4 ld4g(const float* __restrict__ img, int gr, int gc) {
    float4 v = make_float4(0.f, 0.f, 0.f, 0.f);
    if (gr < IMG) {
        const float* row = img + (size_t)gr * IMG;
        if (gc + 3 < IMG) {
            v = *(const float4*)(row + gc);
        } else {
            if (gc     < IMG) v.x = row[gc];
            if (gc + 1 < IMG) v.y = row[gc + 1];
            if (gc + 2 < IMG) v.z = row[gc + 2];
        }
    }
    return v;
}

// Warp-level horizontal 5-sum of one 136-float row: v = cols 4*ln..4*ln+3,
// v2 (lanes 0..1) = cols 128+4*ln..131+4*ln. Writes h[0..131] (or h[0..127]).
__device__ __forceinline__ void hrow_sum(float4 v, float4 v2, float* hrow, int ln,
                                         bool store_extra) {
    const unsigned m = 0xFFFFFFFFu;
    float4 n;
    n.x = __shfl_down_sync(m, v.x, 1);
    n.y = __shfl_down_sync(m, v.y, 1);
    n.z = __shfl_down_sync(m, v.z, 1);
    n.w = __shfl_down_sync(m, v.w, 1);
    float4 b0;
    b0.x = __shfl_sync(m, v2.x, 0);
    b0.y = __shfl_sync(m, v2.y, 0);
    b0.z = __shfl_sync(m, v2.z, 0);
    b0.w = __shfl_sync(m, v2.w, 0);
    if (ln == 31) n = b0;               // lane 31's right neighbor = cols 128..131

    float h0 = (v.x + v.y) + (v.z + v.w) + n.x;
    float h1 = h0 - v.x + n.y;
    float h2 = h1 - v.y + n.z;
    float h3 = h2 - v.z + n.w;
    *(float4*)(hrow + 4 * ln) = make_float4(h0, h1, h2, h3);

    if (store_extra) {
        float4 b1;
        b1.x = __shfl_sync(m, v2.x, 1);  // cols 132..135
        b1.y = __shfl_sync(m, v2.y, 1);
        b1.z = __shfl_sync(m, v2.z, 1);
        b1.w = __shfl_sync(m, v2.w, 1);
        if (ln == 0) {
            float g0 = (v2.x + v2.y) + (v2.z + v2.w) + b1.x;
            float g1 = g0 - v2.x + b1.y;
            float g2 = g1 - v2.y + b1.z;
            float g3 = g2 - v2.z + b1.w;
            *(float4*)(hrow + 128) = make_float4(g0, g1, g2, g3);
        }
    }
}

__global__ __launch_bounds__(NT, 4) void cov_kernel(
    const float* __restrict__ x, const float* __restrict__ y,
    float* __restrict__ out)
{
    extern __shared__ float sm[];
    float* hA = sm;              // [IN_H][HS] : h-sums of x; product written in place
    float* hB = sm + IN_H * HS;  // [IN_H][HS] : h-sums of y; later hprod

    const int bx  = blockIdx.x * TILE_W;
    const int by  = blockIdx.y * TILE_H;
    const int n   = blockIdx.z;
    const int tid = threadIdx.x;
    const int wid = tid >> 5;
    const int ln  = tid & 31;

    const size_t ibase = (size_t)n * IMG * IMG;
    const float* xp = x + ibase;
    const float* yp = y + ibase;
    const float4 z4 = make_float4(0.f, 0.f, 0.f, 0.f);

    // ---- Phase 1: global load + warp-shuffle horizontal 5-sums for x and y ----
    for (int r = wid; r < IN_H; r += NW) {
        const int gr = by + r;
        float4 vx  = ld4g(xp, gr, bx + 4 * ln);
        float4 vx2 = (ln < 2) ? ld4g(xp, gr, bx + 128 + 4 * ln) : z4;
        hrow_sum(vx, vx2, hA + r * HS, ln, true);
        float4 vy  = ld4g(yp, gr, bx + 4 * ln);
        float4 vy2 = (ln < 2) ? ld4g(yp, gr, bx + 128 + 4 * ln) : z4;
        hrow_sum(vy, vy2, hB + r * HS, ln, true);
    }
    __syncthreads();

    // ---- Phase 2: vertical 5-sums + deviations + product, thread-pair scheme.
    // Even lane of a pair rolls x's sum over ALL 36 rows of one column (hA),
    // odd lane rolls y's (hB); a 5-deep register ring removes the -old LDS.
    // Product = d * shfl_xor(d,1), stored in place into hA by the even lane.
    // In-place is safe: column q is read only by its own pair, and the write
    // to row p happens after that thread's last read of row p (ring holds it).
    if (tid < 2 * MID_W) {                   // 264 workers
        const int q    = tid >> 1;           // column 0..131
        const int side = tid & 1;            // 0: x/hA, 1: y/hB
        const unsigned pmask = (tid >= 256) ? 0xFFu : 0xFFFFFFFFu;

        const float* cbuf = (side ? hB : hA) + q;
        const float* cimg = side ? yp : xp;

        float rg[5];
        rg[0] = cbuf[0*HS]; rg[1] = cbuf[1*HS]; rg[2] = cbuf[2*HS];
        rg[3] = cbuf[3*HS]; rg[4] = cbuf[4*HS];
        float s = ((rg[0] + rg[1]) + (rg[2] + rg[3])) + rg[4];

        const int  gc     = bx + q + 2;
        const bool gcok   = (gc < IMG);
        const int  rowlim = IMG - (by + 2);          // #valid center rows
        const float* cp = cimg + (size_t)(by + 2) * IMG + gc;
        float* pc = hA + q;

        #pragma unroll
        for (int p = 0; p < MID_H; ++p) {
            const bool ok = gcok && (p < rowlim);
            float cv = ok ? cp[(size_t)p * IMG] : 0.f;   // L2-hit center re-read
            float d  = cv - s * 0.04f;
            float dp = __shfl_xor_sync(pmask, d, 1);
            if (side == 0) pc[p * HS] = d * dp;          // in-place product
            if (p < MID_H - 1) {
                float nw = cbuf[(p + 5) * HS];
                s += nw - rg[p % 5];
                rg[p % 5] = nw;
            }
        }
    }
    __syncthreads();

    // ---- Phase 3: horizontal 5-sum of product (hA rows 0..35) -> hB ----
    for (int p = wid; p < MID_H; p += NW) {
        const float* row = hA + p * HS;
        float4 v  = *(const float4*)(row + 4 * ln);
        float4 v2 = (ln == 0) ? *(const float4*)(row + 128) : z4;
        hrow_sum(v, v2, hB + p * HS, ln, false);
    }
    __syncthreads();

    // ---- Phase 4: vertical 5-sum * 1/25 -> global store (register ring) ----
    if (tid < 256) {
        const int j  = tid & 127;
        const int s2 = tid >> 7;               // strip 0/1
        const int i0 = s2 * (TILE_H / 2);      // 0 or 16
        const int ox = bx + j;
        const float* hc = hB + j;

        float rg[5];
        rg[0] = hc[(i0  )*HS]; rg[1] = hc[(i0+1)*HS]; rg[2] = hc[(i0+2)*HS];
        rg[3] = hc[(i0+3)*HS]; rg[4] = hc[(i0+4)*HS];
        float m = ((rg[0] + rg[1]) + (rg[2] + rg[3])) + rg[4];

        float* ob = out + (size_t)n * OUTD * OUTD;
        #pragma unroll
        for (int k = 0; k < TILE_H / 2; ++k) {
            const int i  = i0 + k;
            const int oy = by + i;
            if (ox < OUTD && oy < OUTD)
                ob[(size_t)oy * OUTD + ox] = m * 0.04f;
            if (k < TILE_H / 2 - 1) {
                float nw = hc[(i + 5) * HS];
                m += nw - rg[k % 5];
                rg[k % 5] = nw;
            }
        }
    }
}

extern "C" void kernel_launch(void* const* d_in, const int* in_sizes, int n_in,
                              void* d_out, int out_size) {
    const float* x = (const float*)d_in[0];
    const float* y = (const float*)d_in[1];
    // d_in[2] = mean_mask (uniform 1/25, folded into the 0.04f constants)
    float* out = (float*)d_out;

    const int smem = 2 * IN_H * HS * (int)sizeof(float);   // 43520 B
    cudaFuncSetAttribute(cov_kernel, cudaFuncAttributeMaxDynamicSharedMemorySize, smem);

    dim3 grid((OUTD + TILE_W - 1) / TILE_W,    // 8
              (OUTD + TILE_H - 1) / TILE_H,    // 32
              16);
    cov_kernel<<<grid, NT, smem>>>(x, y, out);
}

// round 9
// speedup vs baseline: 1.4505x; 1.4505x over previous
#include <cuda_runtime.h>

#define IMG    1024
#define OUTD   1016
#define TILE_W 128
#define TILE_H 32
#define IN_H   (TILE_H + 8)    // 40 input rows
#define MID_W  132             // horizontal-sum cols
#define MID_H  (TILE_H + 4)    // 36 deviation rows
#define HS     136             // smem row stride (floats)
#define NT     320
#define NW     (NT / 32)       // 10 warps
#define HALFH  (MID_H / 2)     // 18 rows per phase-2 strip

__device__ __forceinline__ float4 ld4g(const float* __restrict__ img, int gr, int gc) {
    float4 v = make_float4(0.f, 0.f, 0.f, 0.f);
    if (gr < IMG) {
        const float* row = img + (size_t)gr * IMG;
        if (gc + 3 < IMG) {
            v = *(const float4*)(row + gc);
        } else {
            if (gc     < IMG) v.x = row[gc];
            if (gc + 1 < IMG) v.y = row[gc + 1];
            if (gc + 2 < IMG) v.z = row[gc + 2];
        }
    }
    return v;
}

// Warp-level horizontal 5-sum of one 136-float row: v = cols 4*ln..4*ln+3,
// v2 (lanes 0..1) = cols 128+4*ln..131+4*ln. Writes h[0..131] (or h[0..127]).
__device__ __forceinline__ void hrow_sum(float4 v, float4 v2, float* hrow, int ln,
                                         bool store_extra) {
    const unsigned m = 0xFFFFFFFFu;
    float4 n;
    n.x = __shfl_down_sync(m, v.x, 1);
    n.y = __shfl_down_sync(m, v.y, 1);
    n.z = __shfl_down_sync(m, v.z, 1);
    n.w = __shfl_down_sync(m, v.w, 1);
    float4 b0;
    b0.x = __shfl_sync(m, v2.x, 0);
    b0.y = __shfl_sync(m, v2.y, 0);
    b0.z = __shfl_sync(m, v2.z, 0);
    b0.w = __shfl_sync(m, v2.w, 0);
    if (ln == 31) n = b0;               // lane 31's right neighbor = cols 128..131

    float h0 = (v.x + v.y) + (v.z + v.w) + n.x;
    float h1 = h0 - v.x + n.y;
    float h2 = h1 - v.y + n.z;
    float h3 = h2 - v.z + n.w;
    *(float4*)(hrow + 4 * ln) = make_float4(h0, h1, h2, h3);

    if (store_extra) {
        float4 b1;
        b1.x = __shfl_sync(m, v2.x, 1);  // cols 132..135
        b1.y = __shfl_sync(m, v2.y, 1);
        b1.z = __shfl_sync(m, v2.z, 1);
        b1.w = __shfl_sync(m, v2.w, 1);
        if (ln == 0) {
            float g0 = (v2.x + v2.y) + (v2.z + v2.w) + b1.x;
            float g1 = g0 - v2.x + b1.y;
            float g2 = g1 - v2.y + b1.z;
            float g3 = g2 - v2.z + b1.w;
            *(float4*)(hrow + 128) = make_float4(g0, g1, g2, g3);
        }
    }
}

__global__ __launch_bounds__(NT, 4) void cov_kernel(
    const float* __restrict__ x, const float* __restrict__ y,
    float* __restrict__ out)
{
    extern __shared__ float sm[];
    float* hA = sm;              // [IN_H][HS] : h-sums of x; D written at row p+4
    float* hB = sm + IN_H * HS;  // [IN_H][HS] : h-sums of y; later hprod

    const int bx  = blockIdx.x * TILE_W;
    const int by  = blockIdx.y * TILE_H;
    const int n   = blockIdx.z;
    const int tid = threadIdx.x;
    const int wid = tid >> 5;
    const int ln  = tid & 31;

    const size_t ibase = (size_t)n * IMG * IMG;
    const float* xp = x + ibase;
    const float* yp = y + ibase;
    const float4 z4 = make_float4(0.f, 0.f, 0.f, 0.f);

    // ---- Phase 1: global load + warp-shuffle horizontal 5-sums for x and y ----
    for (int r = wid; r < IN_H; r += NW) {
        const int gr = by + r;
        float4 vx  = ld4g(xp, gr, bx + 4 * ln);
        float4 vx2 = (ln < 2) ? ld4g(xp, gr, bx + 128 + 4 * ln) : z4;
        hrow_sum(vx, vx2, hA + r * HS, ln, true);
        float4 vy  = ld4g(yp, gr, bx + 4 * ln);
        float4 vy2 = (ln < 2) ? ld4g(yp, gr, bx + 128 + 4 * ln) : z4;
        hrow_sum(vy, vy2, hB + r * HS, ln, true);
    }
    __syncthreads();

    // ---- Phase 2: vertical 5-sums + deviations; D[p] written to hA row p+4.
    // Register rings (rgA/rgB) remove the "-old" smem reads of the rolling sum.
    // Row-shift makes strips disjoint in hA: strip 0 reads rows 0..21 / writes
    // 4..21; strip 1 writes 22..39 and post-sync reads only rows 23..39 (its
    // init rows 18..22 are captured in the ring BEFORE the guarding sync).
    const int q     = tid % MID_W;
    const int strip = tid / MID_W;
    const bool act  = tid < 2 * MID_W;      // 264 workers
    const int p0    = strip * HALFH;        // 0 or 18

    const float* cA = hA + q;
    const float* cB = hB + q;
    float rgA[5], rgB[5];
    float sA = 0.f, sB = 0.f;

    if (act) {
        #pragma unroll
        for (int k = 0; k < 5; ++k) {
            rgA[k] = cA[(p0 + k) * HS];
            rgB[k] = cB[(p0 + k) * HS];
        }
        sA = ((rgA[0] + rgA[1]) + (rgA[2] + rgA[3])) + rgA[4];
        sB = ((rgB[0] + rgB[1]) + (rgB[2] + rgB[3])) + rgB[4];
    }
    __syncthreads();   // ring init (incl. strip 1's rows 18..22) before any D write

    if (act) {
        const int  gc     = bx + q + 2;
        const bool gcok   = (gc < IMG);
        const int  rowlim = IMG - (by + p0 + 2);        // #valid center rows
        const float* xc = xp + (size_t)(by + p0 + 2) * IMG + gc;
        const float* yc = yp + (size_t)(by + p0 + 2) * IMG + gc;
        float* pc = hA + q;

        #pragma unroll
        for (int k = 0; k < HALFH; ++k) {
            const int p  = p0 + k;
            const bool ok = gcok && (k < rowlim);
            float xv = ok ? xc[(size_t)k * IMG] : 0.f;   // L2-hit center re-read
            float yv = ok ? yc[(size_t)k * IMG] : 0.f;
            float dA = xv - sA * 0.04f;
            float dB = yv - sB * 0.04f;
            pc[(p + 4) * HS] = dA * dB;                  // D at shifted row p+4
            if (k < HALFH - 1) {
                float nwA = cA[(p + 5) * HS];
                float nwB = cB[(p + 5) * HS];
                sA += nwA - rgA[k % 5];  rgA[k % 5] = nwA;
                sB += nwB - rgB[k % 5];  rgB[k % 5] = nwB;
            }
        }
    }
    __syncthreads();

    // ---- Phase 3: horizontal 5-sum of product (hA rows 4..39) -> hB rows 0..35 ----
    for (int p = wid; p < MID_H; p += NW) {
        const float* row = hA + (p + 4) * HS;
        float4 v  = *(const float4*)(row + 4 * ln);
        float4 v2 = (ln == 0) ? *(const float4*)(row + 128) : z4;
        hrow_sum(v, v2, hB + p * HS, ln, false);
    }
    __syncthreads();

    // ---- Phase 4: vertical 5-sum * 1/25 -> global store (register ring) ----
    if (tid < 256) {
        const int j  = tid & 127;
        const int s2 = tid >> 7;               // strip 0/1
        const int i0 = s2 * (TILE_H / 2);      // 0 or 16
        const int ox = bx + j;
        const float* hc = hB + j;

        float rg[5];
        rg[0] = hc[(i0  )*HS]; rg[1] = hc[(i0+1)*HS]; rg[2] = hc[(i0+2)*HS];
        rg[3] = hc[(i0+3)*HS]; rg[4] = hc[(i0+4)*HS];
        float m = ((rg[0] + rg[1]) + (rg[2] + rg[3])) + rg[4];

        float* ob = out + (size_t)n * OUTD * OUTD;
        #pragma unroll
        for (int k = 0; k < TILE_H / 2; ++k) {
            const int i  = i0 + k;
            const int oy = by + i;
            if (ox < OUTD && oy < OUTD)
                ob[(size_t)oy * OUTD + ox] = m * 0.04f;
            if (k < TILE_H / 2 - 1) {
                float nw = hc[(i + 5) * HS];
                m += nw - rg[k % 5];
                rg[k % 5] = nw;
            }
        }
    }
}

extern "C" void kernel_launch(void* const* d_in, const int* in_sizes, int n_in,
                              void* d_out, int out_size) {
    const float* x = (const float*)d_in[0];
    const float* y = (const float*)d_in[1];
    // d_in[2] = mean_mask (uniform 1/25, folded into the 0.04f constants)
    float* out = (float*)d_out;

    const int smem = 2 * IN_H * HS * (int)sizeof(float);   // 43520 B
    cudaFuncSetAttribute(cov_kernel, cudaFuncAttributeMaxDynamicSharedMemorySize, smem);

    dim3 grid((OUTD + TILE_W - 1) / TILE_W,    // 8
              (OUTD + TILE_H - 1) / TILE_H,    // 32
              16);
    cov_kernel<<<grid, NT, smem>>>(x, y, out);
}

// round 10
// speedup vs baseline: 1.4621x; 1.0080x over previous
#include <cuda_runtime.h>

#define IMG    1024
#define OUTD   1016
#define TILE_W 128
#define TILE_H 32
#define IN_H   (TILE_H + 8)    // 40 input rows
#define MID_W  132             // horizontal-sum cols
#define MID_H  (TILE_H + 4)    // 36 deviation rows
#define HS     136             // smem row stride (floats)
#define NT     320
#define NW     (NT / 32)       // 10 warps
#define HALFH  (MID_H / 2)     // 18 rows per phase-2 strip

__device__ __forceinline__ float4 ld4g(const float* __restrict__ img, int gr, int gc) {
    float4 v = make_float4(0.f, 0.f, 0.f, 0.f);
    if (gr < IMG) {
        const float* row = img + (size_t)gr * IMG;
        if (gc + 3 < IMG) {
            v = *(const float4*)(row + gc);
        } else {
            if (gc     < IMG) v.x = row[gc];
            if (gc + 1 < IMG) v.y = row[gc + 1];
            if (gc + 2 < IMG) v.z = row[gc + 2];
        }
    }
    return v;
}

// Warp-level horizontal 5-sum of one 136-float row: v = cols 4*ln..4*ln+3,
// v2 (lanes 0..1) = cols 128+4*ln..131+4*ln. Writes h[0..131] (or h[0..127]).
__device__ __forceinline__ void hrow_sum(float4 v, float4 v2, float* hrow, int ln,
                                         bool store_extra) {
    const unsigned m = 0xFFFFFFFFu;
    float4 n;
    n.x = __shfl_down_sync(m, v.x, 1);
    n.y = __shfl_down_sync(m, v.y, 1);
    n.z = __shfl_down_sync(m, v.z, 1);
    n.w = __shfl_down_sync(m, v.w, 1);
    float4 b0;
    b0.x = __shfl_sync(m, v2.x, 0);
    b0.y = __shfl_sync(m, v2.y, 0);
    b0.z = __shfl_sync(m, v2.z, 0);
    b0.w = __shfl_sync(m, v2.w, 0);
    if (ln == 31) n = b0;               // lane 31's right neighbor = cols 128..131

    float h0 = (v.x + v.y) + (v.z + v.w) + n.x;
    float h1 = h0 - v.x + n.y;
    float h2 = h1 - v.y + n.z;
    float h3 = h2 - v.z + n.w;
    *(float4*)(hrow + 4 * ln) = make_float4(h0, h1, h2, h3);

    if (store_extra) {
        float4 b1;
        b1.x = __shfl_sync(m, v2.x, 1);  // cols 132..135
        b1.y = __shfl_sync(m, v2.y, 1);
        b1.z = __shfl_sync(m, v2.z, 1);
        b1.w = __shfl_sync(m, v2.w, 1);
        if (ln == 0) {
            float g0 = (v2.x + v2.y) + (v2.z + v2.w) + b1.x;
            float g1 = g0 - v2.x + b1.y;
            float g2 = g1 - v2.y + b1.z;
            float g3 = g2 - v2.z + b1.w;
            *(float4*)(hrow + 128) = make_float4(g0, g1, g2, g3);
        }
    }
}

__global__ __launch_bounds__(NT, 5) void cov_kernel(
    const float* __restrict__ x, const float* __restrict__ y,
    float* __restrict__ out)
{
    extern __shared__ float sm[];
    float* hA = sm;              // [IN_H][HS] : h-sums of x; D written at row p+4
    float* hB = sm + IN_H * HS;  // [IN_H][HS] : h-sums of y; later hprod

    const int bx  = blockIdx.x * TILE_W;
    const int by  = blockIdx.y * TILE_H;
    const int n   = blockIdx.z;
    const int tid = threadIdx.x;
    const int wid = tid >> 5;
    const int ln  = tid & 31;

    const size_t ibase = (size_t)n * IMG * IMG;
    const float* xp = x + ibase;
    const float* yp = y + ibase;
    const float4 z4 = make_float4(0.f, 0.f, 0.f, 0.f);

    // ---- Phase 1: global load + warp-shuffle horizontal 5-sums for x and y ----
    for (int r = wid; r < IN_H; r += NW) {
        const int gr = by + r;
        float4 vx  = ld4g(xp, gr, bx + 4 * ln);
        float4 vx2 = (ln < 2) ? ld4g(xp, gr, bx + 128 + 4 * ln) : z4;
        hrow_sum(vx, vx2, hA + r * HS, ln, true);
        float4 vy  = ld4g(yp, gr, bx + 4 * ln);
        float4 vy2 = (ln < 2) ? ld4g(yp, gr, bx + 128 + 4 * ln) : z4;
        hrow_sum(vy, vy2, hB + r * HS, ln, true);
    }
    __syncthreads();

    // ---- Phase 2: vertical 5-sums + deviations; D[p] written to hA row p+4.
    // Column q is entirely thread-private (reads & writes of col q happen only
    // in the thread owning q), so ordering within the thread is all that
    // matters: row p+5 is read at step p, overwritten (as D) at step p+1; the
    // "-old" term for hA must come from the rgA register ring because row p
    // was destroyed at step p-4. hB is never written in this phase, so its
    // old term is a plain smem re-read (saves 5 registers for the 5-CTA fit).
    const int q     = tid % MID_W;
    const int strip = tid / MID_W;
    const bool act  = tid < 2 * MID_W;      // 264 workers
    const int p0    = strip * HALFH;        // 0 or 18

    const float* cA = hA + q;
    const float* cB = hB + q;
    float rgA[5];
    float sA = 0.f, sB = 0.f;

    if (act) {
        #pragma unroll
        for (int k = 0; k < 5; ++k) rgA[k] = cA[(p0 + k) * HS];
        sA = ((rgA[0] + rgA[1]) + (rgA[2] + rgA[3])) + rgA[4];
        sB = ((cB[(p0)*HS] + cB[(p0+1)*HS]) + (cB[(p0+2)*HS] + cB[(p0+3)*HS]))
           + cB[(p0+4)*HS];
    }
    __syncthreads();   // ring init before any D write (cross-strip row handoff)

    if (act) {
        const int  gc     = bx + q + 2;
        const bool gcok   = (gc < IMG);
        const int  rowlim = IMG - (by + p0 + 2);        // #valid center rows
        const float* xc = xp + (size_t)(by + p0 + 2) * IMG + gc;
        const float* yc = yp + (size_t)(by + p0 + 2) * IMG + gc;
        float* pc = hA + q;

        #pragma unroll
        for (int k = 0; k < HALFH; ++k) {
            const int p  = p0 + k;
            const bool ok = gcok && (k < rowlim);
            float xv = ok ? xc[(size_t)k * IMG] : 0.f;   // L2-hit center re-read
            float yv = ok ? yc[(size_t)k * IMG] : 0.f;
            float dA = xv - sA * 0.04f;
            float dB = yv - sB * 0.04f;
            pc[(p + 4) * HS] = dA * dB;                  // D at shifted row p+4
            if (k < HALFH - 1) {
                float nwA = cA[(p + 5) * HS];
                sA += nwA - rgA[k % 5];  rgA[k % 5] = nwA;
                sB += cB[(p + 5) * HS] - cB[p * HS];     // hB intact: re-read old
            }
        }
    }
    __syncthreads();

    // ---- Phase 3: horizontal 5-sum of product (hA rows 4..39) -> hB rows 0..35 ----
    for (int p = wid; p < MID_H; p += NW) {
        const float* row = hA + (p + 4) * HS;
        float4 v  = *(const float4*)(row + 4 * ln);
        float4 v2 = (ln == 0) ? *(const float4*)(row + 128) : z4;
        hrow_sum(v, v2, hB + p * HS, ln, false);
    }
    __syncthreads();

    // ---- Phase 4: vertical 5-sum * 1/25 -> global store (register ring) ----
    if (tid < 256) {
        const int j  = tid & 127;
        const int s2 = tid >> 7;               // strip 0/1
        const int i0 = s2 * (TILE_H / 2);      // 0 or 16
        const int ox = bx + j;
        const float* hc = hB + j;

        float rg[5];
        rg[0] = hc[(i0  )*HS]; rg[1] = hc[(i0+1)*HS]; rg[2] = hc[(i0+2)*HS];
        rg[3] = hc[(i0+3)*HS]; rg[4] = hc[(i0+4)*HS];
        float m = ((rg[0] + rg[1]) + (rg[2] + rg[3])) + rg[4];

        float* ob = out + (size_t)n * OUTD * OUTD;
        #pragma unroll
        for (int k = 0; k < TILE_H / 2; ++k) {
            const int i  = i0 + k;
            const int oy = by + i;
            if (ox < OUTD && oy < OUTD)
                ob[(size_t)oy * OUTD + ox] = m * 0.04f;
            if (k < TILE_H / 2 - 1) {
                float nw = hc[(i + 5) * HS];
                m += nw - rg[k % 5];
                rg[k % 5] = nw;
            }
        }
    }
}

extern "C" void kernel_launch(void* const* d_in, const int* in_sizes, int n_in,
                              void* d_out, int out_size) {
    const float* x = (const float*)d_in[0];
    const float* y = (const float*)d_in[1];
    // d_in[2] = mean_mask (uniform 1/25, folded into the 0.04f constants)
    float* out = (float*)d_out;

    const int smem = 2 * IN_H * HS * (int)sizeof(float);   // 43520 B
    cudaFuncSetAttribute(cov_kernel, cudaFuncAttributeMaxDynamicSharedMemorySize, smem);

    dim3 grid((OUTD + TILE_W - 1) / TILE_W,    // 8
              (OUTD + TILE_H - 1) / TILE_H,    // 32
              16);
    cov_kernel<<<grid, NT, smem>>>(x, y, out);
}

// round 11
// speedup vs baseline: 1.5484x; 1.0590x over previous
#include <cuda_runtime.h>

#define IMG    1024
#define OUTD   1016
#define TILE_W 128
#define TILE_H 32
#define IN_H   (TILE_H + 8)    // 40 input rows
#define HS     136             // smem row stride (floats)
#define NT     320
#define NW     (NT / 32)       // 10 warps
#define NSTEP  20              // D-rows per strip (16 outputs + 4 warmup)

__device__ __forceinline__ float4 ld4g(const float* __restrict__ img, int gr, int gc) {
    float4 v = make_float4(0.f, 0.f, 0.f, 0.f);
    if (gr < IMG) {
        const float* row = img + (size_t)gr * IMG;
        if (gc + 3 < IMG) {
            v = *(const float4*)(row + gc);
        } else {
            if (gc     < IMG) v.x = row[gc];
            if (gc + 1 < IMG) v.y = row[gc + 1];
            if (gc + 2 < IMG) v.z = row[gc + 2];
        }
    }
    return v;
}

// Warp-level horizontal 5-sum of one 136-float row: v = cols 4*ln..4*ln+3,
// v2 (lanes 0..1) = cols 128+4*ln..131+4*ln. Writes h[0..131].
__device__ __forceinline__ void hrow_sum(float4 v, float4 v2, float* hrow, int ln) {
    const unsigned m = 0xFFFFFFFFu;
    float4 n;
    n.x = __shfl_down_sync(m, v.x, 1);
    n.y = __shfl_down_sync(m, v.y, 1);
    n.z = __shfl_down_sync(m, v.z, 1);
    n.w = __shfl_down_sync(m, v.w, 1);
    float4 b0;
    b0.x = __shfl_sync(m, v2.x, 0);
    b0.y = __shfl_sync(m, v2.y, 0);
    b0.z = __shfl_sync(m, v2.z, 0);
    b0.w = __shfl_sync(m, v2.w, 0);
    if (ln == 31) n = b0;               // lane 31's right neighbor = cols 128..131

    float h0 = (v.x + v.y) + (v.z + v.w) + n.x;
    float h1 = h0 - v.x + n.y;
    float h2 = h1 - v.y + n.z;
    float h3 = h2 - v.z + n.w;
    *(float4*)(hrow + 4 * ln) = make_float4(h0, h1, h2, h3);

    float4 b1;
    b1.x = __shfl_sync(m, v2.x, 1);     // cols 132..135
    b1.y = __shfl_sync(m, v2.y, 1);
    b1.z = __shfl_sync(m, v2.z, 1);
    b1.w = __shfl_sync(m, v2.w, 1);
    if (ln == 0) {
        float g0 = (v2.x + v2.y) + (v2.z + v2.w) + b1.x;
        float g1 = g0 - v2.x + b1.y;
        float g2 = g1 - v2.y + b1.z;
        float g3 = g2 - v2.z + b1.w;
        *(float4*)(hrow + 128) = make_float4(g0, g1, g2, g3);
    }
}

__global__ __launch_bounds__(NT, 4) void cov_kernel(
    const float* __restrict__ x, const float* __restrict__ y,
    float* __restrict__ out)
{
    extern __shared__ float sm[];
    float* hA = sm;              // [IN_H][HS] : horizontal 5-sums of x (read-only after P1)
    float* hB = sm + IN_H * HS;  // [IN_H][HS] : horizontal 5-sums of y

    const int bx  = blockIdx.x * TILE_W;
    const int by  = blockIdx.y * TILE_H;
    const int n   = blockIdx.z;
    const int tid = threadIdx.x;
    const int wid = tid >> 5;
    const int ln  = tid & 31;

    const size_t ibase = (size_t)n * IMG * IMG;
    const float* xp = x + ibase;
    const float* yp = y + ibase;
    const float4 z4 = make_float4(0.f, 0.f, 0.f, 0.f);

    // ---- Phase 1: global load + warp-shuffle horizontal 5-sums for x and y ----
    for (int r = wid; r < IN_H; r += NW) {
        const int gr = by + r;
        float4 vx  = ld4g(xp, gr, bx + 4 * ln);
        float4 vx2 = (ln < 2) ? ld4g(xp, gr, bx + 128 + 4 * ln) : z4;
        hrow_sum(vx, vx2, hA + r * HS, ln);
        float4 vy  = ld4g(yp, gr, bx + 4 * ln);
        float4 vy2 = (ln < 2) ? ld4g(yp, gr, bx + 128 + 4 * ln) : z4;
        hrow_sum(vy, vy2, hB + r * HS, ln);
    }
    __syncthreads();   // the only barrier: hA/hB are read-only from here on

    // ---- Phase 2 (fused): vertical 5-sums, deviation product, horizontal 5-sum
    // of D via 3 warp shuffles, vertical 5-sum of that via register ring, direct
    // global store. Warp layout: wid = strip*5 + wseg; a warp owns 32 D-columns
    // qr = wseg*28 + ln (4-col halo between segments) and 20 D-rows
    // p = p0..p0+19 (strips overlap 4 rows; each yields 16 output rows).
    {
        const unsigned FULL = 0xFFFFFFFFu;
        const int strip = wid / 5;
        const int wseg  = wid % 5;
        const int p0    = strip * 16;            // D-row start (0 or 16)
        const int qr    = wseg * 28 + ln;        // nominal D column (0..139)
        const int q     = qr < 131 ? qr : 131;   // clamp for safe smem reads

        const float* cA = hA + q;
        const float* cB = hB + q;
        float rgA[5], rgB[5], rd[5];
        #pragma unroll
        for (int t = 0; t < 5; ++t) {
            rgA[t] = cA[(p0 + t) * HS];
            rgB[t] = cB[(p0 + t) * HS];
            rd[t]  = 0.f;
        }
        float sA = ((rgA[0] + rgA[1]) + (rgA[2] + rgA[3])) + rgA[4];
        float sB = ((rgB[0] + rgB[1]) + (rgB[2] + rgB[3])) + rgB[4];
        float vd = 0.f;

        const int  gc     = bx + q + 2;
        const bool gcok   = (gc < IMG);
        const int  rowlim = IMG - (by + p0 + 2);     // #valid center rows
        const float* xc = xp + (size_t)(by + p0 + 2) * IMG + gc;
        const float* yc = yp + (size_t)(by + p0 + 2) * IMG + gc;

        // output col = qr (lanes 0..27 only); output row oy = by + p0 + k - 4
        const bool jout = (ln < 28) && (qr < TILE_W) && (bx + qr < OUTD);
        const int  klim = min(NSTEP, OUTD - by - p0 + 4);   // oy < OUTD
        float* ob = out + (size_t)n * OUTD * OUTD + bx + qr;

        #pragma unroll
        for (int k = 0; k < NSTEP; ++k) {
            const bool ok = gcok && (k < rowlim);
            float xv = ok ? xc[(size_t)k * IMG] : 0.f;   // L2-hit center re-read
            float yv = ok ? yc[(size_t)k * IMG] : 0.f;
            float d  = (xv - sA * 0.04f) * (yv - sB * 0.04f);

            // horizontal 5-sum of D across lanes: d[q]+..+d[q+4] in 3 shuffles
            float a  = d + __shfl_down_sync(FULL, d, 1);
            float hd = a + __shfl_down_sync(FULL, a, 2)
                         + __shfl_down_sync(FULL, d, 4);

            vd += hd - rd[k % 5];
            rd[k % 5] = hd;

            if (k >= 4 && k < klim && jout)
                ob[(size_t)(by + p0 + k - 4) * OUTD] = vd * 0.04f;

            if (k < NSTEP - 1) {
                float nwA = cA[(p0 + k + 5) * HS];
                sA += nwA - rgA[k % 5];  rgA[k % 5] = nwA;
                float nwB = cB[(p0 + k + 5) * HS];
                sB += nwB - rgB[k % 5];  rgB[k % 5] = nwB;
            }
        }
    }
}

extern "C" void kernel_launch(void* const* d_in, const int* in_sizes, int n_in,
                              void* d_out, int out_size) {
    const float* x = (const float*)d_in[0];
    const float* y = (const float*)d_in[1];
    // d_in[2] = mean_mask (uniform 1/25, folded into the 0.04f constants)
    float* out = (float*)d_out;

    const int smem = 2 * IN_H * HS * (int)sizeof(float);   // 43520 B
    cudaFuncSetAttribute(cov_kernel, cudaFuncAttributeMaxDynamicSharedMemorySize, smem);

    dim3 grid((OUTD + TILE_W - 1) / TILE_W,    // 8
              (OUTD + TILE_H - 1) / TILE_H,    // 32
              16);
    cov_kernel<<<grid, NT, smem>>>(x, y, out);
}